// round 17
// baseline (speedup 1.0000x reference)
#include <cuda_runtime.h>
#include <cstdint>
#include <math.h>

#define N_ROWS 65536
#define DIM    512
#define KCODES 1024

#define QUANT_OFF 1
#define PERP_OFF  (1 + N_ROWS * DIM)
#define ENC_OFF   (2 + (size_t)N_ROWS * DIM)

// CTA = 64 rows x 1024 codes (8 nc x 8 kc chunks); 2 CTAs/SM
#define BM 64
#define BN 128
#define KC 64                  // k per chunk
#define NCTAS (N_ROWS / BM)    // 1024

// smem byte offsets (per CTA)
#define SM_A    0              // 2 x [64 rows][64 k] f32 = 2 x 16384
#define SM_ABUF 16384
#define SM_B    32768          // 2 x [128 codes][64 k] f32 (xor-swizzled) = 2 x 32768
#define SM_BBUF 32768
#define SM_WN   98304          // 128 f32 (reused as double[8] late)
#define SM_XN   98816          // 64 f32
#define SM_BEST 99072          // 64 u64
#define SM_PART 99584          // 256 f32 xnorm partials (reused as flag late)
#define SM_TOT  100608

// ---- scratch ----
__device__ float  g_wnorm[KCODES];
__device__ int    g_counts[KCODES];
__device__ double g_sse;
__device__ int    g_done;

// ---- helpers ----
static __device__ __forceinline__ uint64_t cvta_g(const void* p) {
    uint64_t a; asm("cvta.to.global.u64 %0, %1;" : "=l"(a) : "l"(p)); return a;
}
static __device__ __forceinline__ uint32_t smem_u32(const void* p) {
    uint32_t a;
    asm("{ .reg .u64 t; cvta.to.shared.u64 t, %1; cvt.u32.u64 %0, t; }" : "=r"(a) : "l"(p));
    return a;
}
static __device__ __forceinline__ void cp16(uint32_t s, uint64_t g) {
    asm volatile("cp.async.cg.shared.global [%0], [%1], 16;" :: "r"(s), "l"(g));
}
#define CP_COMMIT() asm volatile("cp.async.commit_group;")
#define CP_WAIT(n)  asm volatile("cp.async.wait_group %0;" :: "n"(n))

// packed fp32x2 FMA: lanes accumulate independent (even-k, odd-k) partial dots
static __device__ __forceinline__ void fma2(unsigned long long& c,
                                            unsigned long long a,
                                            unsigned long long b) {
    asm("fma.rn.f32x2 %0, %1, %2, %0;" : "+l"(c) : "l"(a), "l"(b));
}
static __device__ __forceinline__ float unpack_sum(unsigned long long v) {
    float lo, hi;
    asm("mov.b64 {%0,%1}, %2;" : "=f"(lo), "=f"(hi) : "l"(v));
    return lo + hi;
}

// ============================================================
// prep: wnorm per code + zero counts/sse  (W only: ~2MB read)
// ============================================================
__global__ void vq_prep_kernel(const float* __restrict__ W) {
    int w = threadIdx.x >> 5, lane = threadIdx.x & 31;
    int code = blockIdx.x * 8 + w;
    const float* row = W + (size_t)code * DIM;
    float s = 0.f;
#pragma unroll
    for (int t = 0; t < DIM / 32; t++) { float v = row[lane + t * 32]; s += v * v; }
#pragma unroll
    for (int o = 16; o > 0; o >>= 1) s += __shfl_down_sync(0xffffffffu, s, o);
    if (lane == 0) g_wnorm[code] = s;
    if (blockIdx.x == 0) {
        for (int i = threadIdx.x; i < KCODES; i += blockDim.x) g_counts[i] = 0;
        if (threadIdx.x == 0) g_sse = 0.0;
    }
}

// ============================================================
// chunk staging
// ============================================================
static __device__ __forceinline__ void stage_a(
    uint32_t sb, const float* __restrict__ X, int r0, int kc, int buf, int tid)
{
    uint64_t xsrc = cvta_g(X) + (size_t)r0 * (DIM * 4) + kc * (KC * 4);
    uint32_t dst = sb + SM_A + buf * SM_ABUF;
#pragma unroll
    for (int i = 0; i < 4; i++) {
        int f = tid + i * 256;          // 0..1023
        int row = f >> 4, k4 = f & 15;
        cp16(dst + row * 256 + k4 * 16,
             xsrc + (size_t)row * (DIM * 4) + k4 * 16);
    }
}
static __device__ __forceinline__ void stage_b(
    uint32_t sb, const float* __restrict__ W, int c0, int kc, int buf, int tid)
{
    uint64_t wsrc = cvta_g(W) + (size_t)c0 * (DIM * 4) + kc * (KC * 4);
    uint32_t dst = sb + SM_B + buf * SM_BBUF;
#pragma unroll
    for (int i = 0; i < 8; i++) {
        int f = tid + i * 256;          // 0..2047
        int code = f >> 4, k4 = f & 15;
        int col = k4 ^ (code & 15);
        cp16(dst + code * 256 + col * 16,
             wsrc + (size_t)code * (DIM * 4) + k4 * 16);
    }
}

// ============================================================
// main: f32x2 exact GEMM + fused argmin + fused output + fused finalize
// 256 thr = 8(tr) x 32(tc); thread = 8 rows x 4 codes (cols j*32+tc)
// single __syncthreads per chunk (distance-1 prefetch)
// ============================================================
__global__ void __launch_bounds__(256, 2)
vq_main(const float* __restrict__ X, const float* __restrict__ W,
        float* __restrict__ out, float* __restrict__ outq,
        float* __restrict__ oute) {
    extern __shared__ __align__(16) char smem[];
    const uint32_t sb = smem_u32(smem);
    float* sWn = (float*)(smem + SM_WN);
    float* sXn = (float*)(smem + SM_XN);
    unsigned long long* sBest = (unsigned long long*)(smem + SM_BEST);
    float* sPart = (float*)(smem + SM_PART);

    const int tid = threadIdx.x;
    const int tr = tid >> 5, tc = tid & 31;
    const int r0 = blockIdx.x * BM;

    // prologue: chunk 0 into buf0
    stage_a(sb, X, r0, 0, 0, tid);
    stage_b(sb, W, 0, 0, 0, tid);
    CP_COMMIT();

    if (tid < BM) sBest[tid] = 0xFFFFFFFFFFFFFFFFull;

    // encodings zero-fill for this CTA's rows (idx-independent; overlaps compute)
    {
        float2 z2 = make_float2(0.f, 0.f);
        for (int f = tid; f < BM * (KCODES / 2); f += 256) {
            int row = f >> 9, q = f & 511;
            ((float2*)(oute + (size_t)(r0 + row) * KCODES))[q] = z2;
        }
    }

    unsigned long long acc[8][4];
    float xpart = 0.f;                   // xnorm partial (row tid>>2, part tid&3)

    for (int t = 0; t < 64; t++) {
        const int nc = t >> 3, kc = t & 7, buf = t & 1;
        CP_WAIT(0);                      // chunk t landed
        __syncthreads();                 // + all warps done with compute(t-1)

        if (t + 1 < 64) {                // prefetch t+1 into buf^1 (old, drained)
            const int nt = t + 1;
            stage_a(sb, X, r0, nt & 7, buf ^ 1, tid);
            stage_b(sb, W, (nt >> 3) * BN, nt & 7, buf ^ 1, tid);
            CP_COMMIT();
        }

        if (t < 8) {                     // nc==0: accumulate xnorm from A chunks
            const float* ax = (const float*)(smem + SM_A + buf * SM_ABUF)
                              + (tid >> 2) * KC + (tid & 3) * 16;
#pragma unroll
            for (int q = 0; q < 16; q++) { float v = ax[q]; xpart += v * v; }
            if (t == 7) {                // full k covered: reduce to sXn
                sPart[tid] = xpart;
                __syncthreads();
                if (tid < BM) {
                    float* p = sPart + tid * 4;
                    sXn[tid] = (p[0] + p[1]) + (p[2] + p[3]);
                }
                __syncthreads();
            }
        }

        if (kc == 0) {
            if (tid < BN) sWn[tid] = g_wnorm[nc * BN + tid];
#pragma unroll
            for (int i = 0; i < 8; i++)
#pragma unroll
                for (int j = 0; j < 4; j++) acc[i][j] = 0ull;
        }

        const char* pB = smem + SM_B + buf * SM_BBUF;
        const float* pA = (const float*)(smem + SM_A + buf * SM_ABUF)
                          + (tr * 8) * KC;
#pragma unroll
        for (int k4 = 0; k4 < 16; k4++) {
            const int col16 = (k4 ^ (tc & 15)) << 4;
            ulonglong2 bv[4];
#pragma unroll
            for (int j = 0; j < 4; j++)
                bv[j] = *(const ulonglong2*)(pB + (j * 32 + tc) * 256 + col16);
#pragma unroll
            for (int i = 0; i < 8; i++) {
                ulonglong2 av = *(const ulonglong2*)(pA + i * KC + k4 * 4);
#pragma unroll
                for (int j = 0; j < 4; j++)
                    fma2(acc[i][j], av.x, bv[j].x);
#pragma unroll
                for (int j = 0; j < 4; j++)
                    fma2(acc[i][j], av.y, bv[j].y);
            }
        }

        if (kc == 7) {
            // ---- epilogue: distances + per-row argmin (first-index ties) ----
            const int c0 = nc * BN;
#pragma unroll
            for (int i = 0; i < 8; i++) {
                int row = tr * 8 + i;
                float xn = sXn[row];
                unsigned long long best = 0xFFFFFFFFFFFFFFFFull;
#pragma unroll
                for (int j = 0; j < 4; j++) {
                    int col = j * 32 + tc;
                    float dot = unpack_sum(acc[i][j]);
                    float d = (xn + sWn[col]) - 2.0f * dot;   // reference formula
                    unsigned key = __float_as_uint(d);
                    key = (key & 0x80000000u) ? ~key : (key | 0x80000000u);
                    unsigned long long pk =
                        ((unsigned long long)key << 32) | (unsigned)(c0 + col);
                    if (pk < best) best = pk;
                }
                atomicMin(&sBest[row], best);
            }
        }
    }

    __syncthreads();                     // argmins final; zero-fill ordered before
    if (tid < BM) {
        int idx = (int)(sBest[tid] & 0xFFFFFFFFu);
        atomicAdd(&g_counts[idx], 1);
        oute[(size_t)(r0 + tid) * KCODES + idx] = 1.0f;   // one-hot scatter
    }

    // ---- fused output tail: quantized_st + SSE (rows r0..r0+63) ----
    {
        const int sub = tid >> 7, c4 = tid & 127;
        float a0 = 0.f, a1 = 0.f, a2 = 0.f, a3 = 0.f;
#pragma unroll 4
        for (int i = 0; i < 32; i++) {
            int rl = i * 2 + sub;
            int r = r0 + rl;
            int idx = (int)(sBest[rl] & 0xFFFFFFFFu);
            float4 xv = ((const float4*)(X + (size_t)r * DIM))[c4];
            float4 qv = ((const float4*)(W + (size_t)idx * DIM))[c4];
            float dx = qv.x - xv.x, dy = qv.y - xv.y;
            float dz = qv.z - xv.z, dw = qv.w - xv.w;
            float* op = outq + (size_t)r * DIM + c4 * 4;   // 4B-aligned: scalar STG
            op[0] = xv.x + dx; op[1] = xv.y + dy;
            op[2] = xv.z + dz; op[3] = xv.w + dw;
            a0 += dx * dx; a1 += dy * dy; a2 += dz * dz; a3 += dw * dw;
        }
        double lsum = (double)((a0 + a1) + (a2 + a3));
#pragma unroll
        for (int o = 16; o > 0; o >>= 1)
            lsum += __shfl_down_sync(0xffffffffu, lsum, o);
        double* sd = (double*)(smem + SM_WN);   // sWn dead after last epilogue
        __syncthreads();
        if ((tid & 31) == 0) sd[tid >> 5] = lsum;
        __syncthreads();
        if (tid == 0) {
            double s = 0.0;
            for (int v = 0; v < 8; v++) s += sd[v];
            atomicAdd(&g_sse, s);
        }
    }

    // ---- fused finalize: last CTA computes loss + perplexity ----
    int* sFlag = (int*)(smem + SM_PART);
    if (tid == 0) {
        __threadfence();
        sFlag[0] = (atomicAdd(&g_done, 1) == NCTAS - 1) ? 1 : 0;
    }
    __syncthreads();
    if (sFlag[0]) {
        float tacc = 0.f;
#pragma unroll
        for (int q = 0; q < 4; q++) {
            int c = tid + q * 256;
            float p = (float)(*(volatile int*)&g_counts[c]) / 65536.0f;
            tacc += p * logf(p + 1e-10f);
        }
#pragma unroll
        for (int o = 16; o > 0; o >>= 1)
            tacc += __shfl_down_sync(0xffffffffu, tacc, o);
        float* red = (float*)(smem + SM_XN);
        if ((tid & 31) == 0) red[tid >> 5] = tacc;
        __syncthreads();
        if (tid == 0) {
            float v = 0.f;
            for (int w = 0; w < 8; w++) v += red[w];
            out[PERP_OFF] = expf(-v);
            double sse = *(volatile double*)&g_sse;
            float m = (float)(sse / 33554432.0);
            out[0] = m + 0.25f * m;
            g_done = 0;                  // reset for next graph replay
        }
    }
}

// ============================================================
extern "C" void kernel_launch(void* const* d_in, const int* in_sizes, int n_in,
                              void* d_out, int out_size) {
    const float* X = (const float*)d_in[0];
    const float* W = (const float*)d_in[1];
    if (n_in >= 2 && in_sizes[0] == KCODES * DIM && in_sizes[1] == N_ROWS * DIM) {
        const float* t = X; X = W; W = t;
    }
    float* out  = (float*)d_out;
    float* outq = out + QUANT_OFF;
    float* oute = out + ENC_OFF;

    cudaFuncSetAttribute(vq_main,
                         cudaFuncAttributeMaxDynamicSharedMemorySize, SM_TOT);

    vq_prep_kernel<<<128, 256>>>(W);
    vq_main<<<NCTAS, 256, SM_TOT>>>(X, W, out, outq, oute);
}